// round 6
// baseline (speedup 1.0000x reference)
#include <cuda_runtime.h>
#include <cuda_fp16.h>
#include <math.h>
#include <stdint.h>

#define DDIM   2048
#define NEXP   64
#define NCOL   128            // router(64) | noise(64) output columns
#define TM     128            // tokens per CTA
#define KC     64             // K elems per chunk
#define NC     (DDIM / KC)    // 32 chunks
#define NTHREADS 640          // 16 consumer warps + 4 producer warps
#define NPROD  128
#define NCONS_THREADS 512
#define AS     133
#define US     65
#define WSCALE 2048.0f
#define INVSCALE (1.0f / 2048.0f)

#define RSTRIDE 144                    // smem row stride bytes (128B data + 16B pad)
#define APL     (128 * RSTRIDE)        // 18432 B per plane (128 rows)
#define STAGE_A (2 * APL)              // 36864
#define STAGE_BYTES (2 * STAGE_A)      // 73728 (A planes + B planes)
#define STAGES  3
#define SM_RING 1024
#define SMEM_BYTES (SM_RING + STAGES * STAGE_BYTES)   // 222208

// pre-split W planes, scaled by 2048 (router rows 0..63, noise rows 64..127)
__device__ __half g_wp[2][NCOL][DDIM];

// ---------------- helpers ----------------
__device__ __forceinline__ uint32_t smem_u32(const void* p) {
    uint32_t a;
    asm("{ .reg .u64 t; cvta.to.shared.u64 t, %1; cvt.u32.u64 %0, t; }" : "=r"(a) : "l"(p));
    return a;
}
__device__ __forceinline__ void mbar_init(uint32_t a, uint32_t cnt) {
    asm volatile("mbarrier.init.shared.b64 [%0], %1;" :: "r"(a), "r"(cnt) : "memory");
}
__device__ __forceinline__ void mbar_arrive(uint32_t a) {
    asm volatile("mbarrier.arrive.shared.b64 _, [%0];" :: "r"(a) : "memory");
}
__device__ __forceinline__ void mbar_wait(uint32_t a, uint32_t parity) {
    asm volatile(
        "{\n\t.reg .pred P1;\n\t"
        "W%=:\n\t"
        "mbarrier.try_wait.parity.acquire.cta.shared::cta.b64 P1, [%0], %1, 0x989680;\n\t"
        "@P1 bra.uni D%=;\n\t"
        "bra.uni W%=;\n\t"
        "D%=:\n\t}"
        :: "r"(a), "r"(parity) : "memory");
}
// 2-way fp16 split of a float pair (lo,hi) -> 2 f16x2 regs
__device__ __forceinline__ void split2(float lo, float hi, uint32_t& u0, uint32_t& u1) {
    __half2 h0 = __floats2half2_rn(lo, hi);
    float l0 = __half2float(__low2half(h0));
    float hh = __half2float(__high2half(h0));
    __half2 h1 = __floats2half2_rn(lo - l0, hi - hh);
    u0 = *reinterpret_cast<uint32_t*>(&h0);
    u1 = *reinterpret_cast<uint32_t*>(&h1);
}
#define LDSM4(r, a) \
    asm volatile("ldmatrix.sync.aligned.m8n8.x4.shared.b16 {%0,%1,%2,%3}, [%4];" \
        : "=r"((r)[0]), "=r"((r)[1]), "=r"((r)[2]), "=r"((r)[3]) : "r"(a))
#define MMA16816(d, a, b) \
    asm volatile("mma.sync.aligned.m16n8k16.row.col.f32.f16.f16.f32 " \
        "{%0,%1,%2,%3}, {%4,%5,%6,%7}, {%8,%9}, {%0,%1,%2,%3};" \
        : "+f"((d)[0]), "+f"((d)[1]), "+f"((d)[2]), "+f"((d)[3]) \
        : "r"((a)[0]), "r"((a)[1]), "r"((a)[2]), "r"((a)[3]), "r"((b)[0]), "r"((b)[1]))
#define CPASYNC16(dst, src) \
    asm volatile("cp.async.cg.shared.global [%0], [%1], 16;" :: "r"(dst), "l"(src) : "memory")

// ---------------- prep: split W into 2 scaled fp16 planes ----------------
__global__ void prep_w_kernel(const float* __restrict__ rw, const float* __restrict__ nw) {
    int idx = blockIdx.x * blockDim.x + threadIdx.x;
    int r = idx >> 11, k = idx & 2047;
    float v = WSCALE * ((r < NEXP) ? rw[r * DDIM + k] : nw[(r - NEXP) * DDIM + k]);
    __half b0 = __float2half_rn(v);
    __half b1 = __float2half_rn(v - __half2float(b0));
    g_wp[0][r][k] = b0;
    g_wp[1][r][k] = b1;
}

// ---------------- main fused kernel ----------------
extern __shared__ char smem[];

__global__ __launch_bounds__(NTHREADS, 1)
void router_hmma_kernel(const float* __restrict__ x,
                        const float* __restrict__ rb,
                        const float* __restrict__ nb,
                        const float* __restrict__ u,
                        float* __restrict__ out,
                        int M)
{
    const int tid  = threadIdx.x;
    const int wid  = tid >> 5;
    const int lane = tid & 31;
    const int m0   = blockIdx.x * TM;
    const uint32_t sb = smem_u32(smem);

    // mbarriers: full[s] at s*16, empty[s] at s*16+8
    if (tid == 0) {
#pragma unroll
        for (int s = 0; s < STAGES; s++) {
            mbar_init(sb + s * 16, NPROD);             // full: 128 producer arrivals
            mbar_init(sb + s * 16 + 8, NCONS_THREADS); // empty: 512 consumer arrivals
        }
    }
    __syncthreads();

    if (wid >= 16) {
        // ================= PRODUCER (warps 16-19, 128 threads) =================
        const int ptid = tid - NCONS_THREADS;
        for (int c = 0; c < NC; c++) {
            const int s = c % STAGES;
            const uint32_t aA = sb + SM_RING + s * STAGE_BYTES;
            const uint32_t aB = aA + STAGE_A;
            mbar_wait(sb + s * 16 + 8, ((c / STAGES) & 1) ^ 1);   // wait empty

            // B: 2 planes x 128 rows x 8 16B-cells = 2048 cells, 16/thread (async)
#pragma unroll
            for (int i = 0; i < 16; i++) {
                int q = ptid + i * NPROD;
                int pl = q >> 10, rem = q & 1023, row = rem >> 3, cg = rem & 7;
                uint32_t dst = aB + pl * APL + row * RSTRIDE + cg * 16;
                CPASYNC16(dst, &g_wp[pl][row][c * KC + cg * 8]);
            }
            asm volatile("cp.async.commit_group;" ::: "memory");

            // A: 128 rows x 16 float4 = 2048, 16/thread in two batches of 8
#pragma unroll
            for (int h = 0; h < 2; h++) {
                float4 av[8];
#pragma unroll
                for (int i = 0; i < 8; i++) {
                    int q = ptid + (h * 8 + i) * NPROD;
                    int row = q >> 4, kq = q & 15;
                    av[i] = *(const float4*)(x + (size_t)(m0 + row) * DDIM + c * KC + kq * 4);
                }
#pragma unroll
                for (int i = 0; i < 8; i++) {
                    int q = ptid + (h * 8 + i) * NPROD;
                    int row = q >> 4, kq = q & 15;
                    uint32_t p0a, p1a, p0b, p1b;
                    split2(av[i].x, av[i].y, p0a, p1a);
                    split2(av[i].z, av[i].w, p0b, p1b);
                    uint32_t base = (aA - sb) + row * RSTRIDE + kq * 8;
                    *(uint2*)(smem + base + 0 * APL) = make_uint2(p0a, p0b);
                    *(uint2*)(smem + base + 1 * APL) = make_uint2(p1a, p1b);
                }
            }
            asm volatile("cp.async.wait_group 0;" ::: "memory");
            mbar_arrive(sb + s * 16);                              // full
        }
    } else {
        // ================= CONSUMER (warps 0-15, 512 threads) =================
        const int wm = wid >> 2;   // 0..3 -> 32-row slab
        const int wn = wid & 3;    // 0..3 -> 32-col slab

        uint32_t aoff[2], boff[2];
#pragma unroll
        for (int mt = 0; mt < 2; mt++) {
            int row = wm * 32 + mt * 16 + (lane & 7) + 8 * ((lane >> 3) & 1);
            aoff[mt] = (uint32_t)(row * RSTRIDE + 16 * ((lane >> 4) & 1));
        }
#pragma unroll
        for (int ntp = 0; ntp < 2; ntp++) {
            int row = wn * 32 + ntp * 16 + ((lane >> 4) & 1) * 8 + (lane & 7);
            boff[ntp] = (uint32_t)(row * RSTRIDE + 16 * ((lane >> 3) & 1));
        }

        float acc[2][4][4];
#pragma unroll
        for (int mt = 0; mt < 2; mt++)
#pragma unroll
            for (int nt = 0; nt < 4; nt++)
#pragma unroll
                for (int e = 0; e < 4; e++) acc[mt][nt][e] = 0.f;

        for (int c = 0; c < NC; c++) {
            const int s = c % STAGES;
            const uint32_t aA = sb + SM_RING + s * STAGE_BYTES;
            const uint32_t aB = aA + STAGE_A;
            mbar_wait(sb + s * 16, (c / STAGES) & 1);              // wait full

#pragma unroll
            for (int ks = 0; ks < 4; ks++) {
                uint32_t a[2][2][4], b[2][4][2];
#pragma unroll
                for (int pl = 0; pl < 2; pl++)
#pragma unroll
                    for (int mt = 0; mt < 2; mt++)
                        LDSM4(a[pl][mt], aA + pl * APL + ks * 32 + aoff[mt]);
#pragma unroll
                for (int pl = 0; pl < 2; pl++)
#pragma unroll
                    for (int ntp = 0; ntp < 2; ntp++) {
                        uint32_t t4[4];
                        LDSM4(t4, aB + pl * APL + ks * 32 + boff[ntp]);
                        b[pl][2 * ntp][0]     = t4[0];
                        b[pl][2 * ntp][1]     = t4[1];
                        b[pl][2 * ntp + 1][0] = t4[2];
                        b[pl][2 * ntp + 1][1] = t4[3];
                    }
                const int CA[3] = {0, 0, 1};
                const int CB[3] = {0, 1, 0};
#pragma unroll
                for (int q = 0; q < 3; q++)
#pragma unroll
                    for (int mt = 0; mt < 2; mt++)
#pragma unroll
                        for (int nt = 0; nt < 4; nt++)
                            MMA16816(acc[mt][nt], a[CA[q]][mt], b[CB[q]][nt]);
            }
            mbar_arrive(sb + s * 16 + 8);                          // arrive empty
        }

        __syncthreads();   // (consumers + producers) — ring dead, safe to reuse
        float* acc_s = (float*)(smem + SM_RING);
#pragma unroll
        for (int mt = 0; mt < 2; mt++)
#pragma unroll
            for (int nt = 0; nt < 4; nt++) {
                int r   = wm * 32 + mt * 16 + (lane >> 2);
                int col = wn * 32 + nt * 8 + (lane & 3) * 2;
                acc_s[r * AS + col]           = acc[mt][nt][0];
                acc_s[r * AS + col + 1]       = acc[mt][nt][1];
                acc_s[(r + 8) * AS + col]     = acc[mt][nt][2];
                acc_s[(r + 8) * AS + col + 1] = acc[mt][nt][3];
            }
    }
    if (wid >= 16) __syncthreads();   // producers join the same barrier

    // ---- noise_u tile (all threads) ----
    float* acc_s = (float*)(smem + SM_RING);
    float* su    = acc_s + TM * AS;
    {
        const float* ug = u + (size_t)m0 * NEXP;
        for (int q = tid; q < TM * NEXP; q += NTHREADS) {
            int r = q >> 6, cn = q & 63;
            su[r * US + cn] = ug[(size_t)r * NEXP + cn];
        }
    }
    __syncthreads();

    // ---- per-token epilogue ----
    if (tid < TM) {
        const int m = m0 + tid;
        float* row = acc_s + tid * AS;
        const float* urow = su + tid * US;

        float v1 = -INFINITY, v2 = -INFINITY;
        int i1 = 0, i2 = 0;
        for (int e = 0; e < NEXP; e++) {
            float lg = row[e] * INVSCALE + rb[e];
            float nz = row[NEXP + e] * INVSCALE + nb[e];
            float sp = fmaxf(nz, 0.f) + log1pf(expf(-fabsf(nz)));
            float nv = lg + sp * urow[e];
            if (nv > v1) { v2 = v1; i2 = i1; v1 = nv; i1 = e; }
            else if (nv > v2) { v2 = nv; i2 = e; }
        }
        float e2 = expf(v2 - v1);
        float den = 1.f + e2;
        float p1 = 1.f / den;
        float p2 = e2 / den;

        for (int e = 0; e < NEXP; e++) row[e] = 0.f;
        row[i1] = p1;
        row[i2] = p2;

        float* oid = out + (size_t)M * NEXP;
        oid[(size_t)m * 2 + 0] = (float)i1;
        oid[(size_t)m * 2 + 1] = (float)i2;
    }
    __syncthreads();

    // coalesced probability writeback
    for (int t = tid; t < TM * (NEXP / 4); t += NTHREADS) {
        int r = t >> 4;
        int c4 = (t & 15) * 4;
        float4 v = make_float4(acc_s[r * AS + c4 + 0],
                               acc_s[r * AS + c4 + 1],
                               acc_s[r * AS + c4 + 2],
                               acc_s[r * AS + c4 + 3]);
        *(float4*)(out + (size_t)(m0 + r) * NEXP + c4) = v;
    }
}

extern "C" void kernel_launch(void* const* d_in, const int* in_sizes, int n_in,
                              void* d_out, int out_size)
{
    const float* x  = (const float*)d_in[0];
    const float* rw = (const float*)d_in[1];
    const float* rb = (const float*)d_in[2];
    const float* nw = (const float*)d_in[3];
    const float* nb = (const float*)d_in[4];
    const float* u  = (const float*)d_in[5];

    const int M = in_sizes[0] / DDIM;  // 16384

    static bool attr_set = false;
    if (!attr_set) {
        cudaFuncSetAttribute(router_hmma_kernel,
                             cudaFuncAttributeMaxDynamicSharedMemorySize,
                             SMEM_BYTES);
        attr_set = true;
    }

    prep_w_kernel<<<(NCOL * DDIM) / 256, 256>>>(rw, nw);
    router_hmma_kernel<<<M / TM, NTHREADS, SMEM_BYTES>>>(x, rb, nb, u, (float*)d_out, M);
}

// round 7
// speedup vs baseline: 1.0706x; 1.0706x over previous
#include <cuda_runtime.h>
#include <cuda_fp16.h>
#include <math.h>
#include <stdint.h>

#define DDIM   2048
#define NEXP   64
#define NCOL   128            // router(64) | noise(64) output columns
#define TM     64             // tokens per CTA
#define KC     64             // K elems per chunk
#define NC     (DDIM / KC)    // 32 chunks
#define NTHREADS 192          // 4 consumer warps + 2 producer warps
#define NPROD  64
#define NCONS_THREADS 128
#define AS     133
#define US     65
#define WSCALE 2048.0f
#define INVSCALE (1.0f / 2048.0f)

#define RSTRIDE 144                    // smem row stride bytes (128B data + 16B pad)
#define A_PL    (TM  * RSTRIDE)        // 9216  B per A plane (64 rows)
#define B_PL    (NCOL * RSTRIDE)       // 18432 B per B plane (128 rows)
#define STAGE_A (2 * A_PL)             // 18432
#define STAGE_BYTES (STAGE_A + 2 * B_PL)   // 55296
#define STAGES  2
#define SM_RING 1024
#define SMEM_BYTES (SM_RING + STAGES * STAGE_BYTES)   // 111616 (x2 CTAs = 223232)

// pre-split W planes, scaled by 2048 (router rows 0..63, noise rows 64..127)
__device__ __half g_wp[2][NCOL][DDIM];

// ---------------- helpers ----------------
__device__ __forceinline__ uint32_t smem_u32(const void* p) {
    uint32_t a;
    asm("{ .reg .u64 t; cvta.to.shared.u64 t, %1; cvt.u32.u64 %0, t; }" : "=r"(a) : "l"(p));
    return a;
}
__device__ __forceinline__ void mbar_init(uint32_t a, uint32_t cnt) {
    asm volatile("mbarrier.init.shared.b64 [%0], %1;" :: "r"(a), "r"(cnt) : "memory");
}
__device__ __forceinline__ void mbar_arrive(uint32_t a) {
    asm volatile("mbarrier.arrive.shared.b64 _, [%0];" :: "r"(a) : "memory");
}
__device__ __forceinline__ void mbar_wait(uint32_t a, uint32_t parity) {
    asm volatile(
        "{\n\t.reg .pred P1;\n\t"
        "W%=:\n\t"
        "mbarrier.try_wait.parity.acquire.cta.shared::cta.b64 P1, [%0], %1, 0x989680;\n\t"
        "@P1 bra.uni D%=;\n\t"
        "bra.uni W%=;\n\t"
        "D%=:\n\t}"
        :: "r"(a), "r"(parity) : "memory");
}
// 2-way fp16 split of a float pair (lo,hi) -> 2 f16x2 regs
__device__ __forceinline__ void split2(float lo, float hi, uint32_t& u0, uint32_t& u1) {
    __half2 h0 = __floats2half2_rn(lo, hi);
    float l0 = __half2float(__low2half(h0));
    float hh = __half2float(__high2half(h0));
    __half2 h1 = __floats2half2_rn(lo - l0, hi - hh);
    u0 = *reinterpret_cast<uint32_t*>(&h0);
    u1 = *reinterpret_cast<uint32_t*>(&h1);
}
#define LDSM4(r, a) \
    asm volatile("ldmatrix.sync.aligned.m8n8.x4.shared.b16 {%0,%1,%2,%3}, [%4];" \
        : "=r"((r)[0]), "=r"((r)[1]), "=r"((r)[2]), "=r"((r)[3]) : "r"(a))
#define MMA16816(d, a, b) \
    asm volatile("mma.sync.aligned.m16n8k16.row.col.f32.f16.f16.f32 " \
        "{%0,%1,%2,%3}, {%4,%5,%6,%7}, {%8,%9}, {%0,%1,%2,%3};" \
        : "+f"((d)[0]), "+f"((d)[1]), "+f"((d)[2]), "+f"((d)[3]) \
        : "r"((a)[0]), "r"((a)[1]), "r"((a)[2]), "r"((a)[3]), "r"((b)[0]), "r"((b)[1]))
#define CPASYNC16(dst, src) \
    asm volatile("cp.async.cg.shared.global [%0], [%1], 16;" :: "r"(dst), "l"(src) : "memory")

// ---------------- prep: split W into 2 scaled fp16 planes ----------------
__global__ void prep_w_kernel(const float* __restrict__ rw, const float* __restrict__ nw) {
    int idx = blockIdx.x * blockDim.x + threadIdx.x;
    int r = idx >> 11, k = idx & 2047;
    float v = WSCALE * ((r < NEXP) ? rw[r * DDIM + k] : nw[(r - NEXP) * DDIM + k]);
    __half b0 = __float2half_rn(v);
    __half b1 = __float2half_rn(v - __half2float(b0));
    g_wp[0][r][k] = b0;
    g_wp[1][r][k] = b1;
}

// ---------------- main fused kernel ----------------
extern __shared__ char smem[];

__global__ __launch_bounds__(NTHREADS, 2)
void router_hmma_kernel(const float* __restrict__ x,
                        const float* __restrict__ rb,
                        const float* __restrict__ nb,
                        const float* __restrict__ u,
                        float* __restrict__ out,
                        int M)
{
    const int tid  = threadIdx.x;
    const int wid  = tid >> 5;
    const int lane = tid & 31;
    const int m0   = blockIdx.x * TM;
    const uint32_t sb = smem_u32(smem);

    // mbarriers: full[s] at s*16, empty[s] at s*16+8
    if (tid == 0) {
#pragma unroll
        for (int s = 0; s < STAGES; s++) {
            mbar_init(sb + s * 16, NPROD);             // full: 64 producer arrivals
            mbar_init(sb + s * 16 + 8, NCONS_THREADS); // empty: 128 consumer arrivals
        }
    }
    __syncthreads();

    if (wid >= 4) {
        // ================= PRODUCER (warps 4-5, 64 threads) =================
        const int ptid = tid - NCONS_THREADS;
        float4 av[16];
        for (int c = 0; c < NC; c++) {
            const int s = c % STAGES;
            const uint32_t aA = sb + SM_RING + s * STAGE_BYTES;
            const uint32_t aB = aA + STAGE_A;
            mbar_wait(sb + s * 16 + 8, ((c / STAGES) & 1) ^ 1);   // wait empty

            // A: 64 rows x 16 float4 = 1024, 16/thread — all LDGs issued upfront
#pragma unroll
            for (int i = 0; i < 16; i++) {
                int q = ptid + i * NPROD;
                int row = q >> 4, kq = q & 15;
                av[i] = *(const float4*)(x + (size_t)(m0 + row) * DDIM + c * KC + kq * 4);
            }
            // B: 2 planes x 128 rows x 8 16B-cells = 2048 cells, 32/thread (async)
#pragma unroll
            for (int i = 0; i < 32; i++) {
                int q = ptid + i * NPROD;
                int pl = q >> 10, rem = q & 1023, row = rem >> 3, cg = rem & 7;
                uint32_t dst = aB + pl * B_PL + row * RSTRIDE + cg * 16;
                CPASYNC16(dst, &g_wp[pl][row][c * KC + cg * 8]);
            }
            asm volatile("cp.async.commit_group;" ::: "memory");

#pragma unroll
            for (int i = 0; i < 16; i++) {
                int q = ptid + i * NPROD;
                int row = q >> 4, kq = q & 15;
                uint32_t p0a, p1a, p0b, p1b;
                split2(av[i].x, av[i].y, p0a, p1a);
                split2(av[i].z, av[i].w, p0b, p1b);
                uint32_t base = (aA - sb) + row * RSTRIDE + kq * 8;
                *(uint2*)(smem + base + 0 * A_PL) = make_uint2(p0a, p0b);
                *(uint2*)(smem + base + 1 * A_PL) = make_uint2(p1a, p1b);
            }
            asm volatile("cp.async.wait_group 0;" ::: "memory");
            mbar_arrive(sb + s * 16);                              // full
        }
    } else {
        // ================= CONSUMER (warps 0-3, 128 threads) =================
        const int wm = wid >> 1;   // 0..1 -> 32-row slab
        const int wn = wid & 1;    // 0..1 -> 64-col slab

        uint32_t aoff[2], boff[4];
#pragma unroll
        for (int mt = 0; mt < 2; mt++) {
            int row = wm * 32 + mt * 16 + (lane & 7) + 8 * ((lane >> 3) & 1);
            aoff[mt] = (uint32_t)(row * RSTRIDE + 16 * ((lane >> 4) & 1));
        }
#pragma unroll
        for (int ntp = 0; ntp < 4; ntp++) {
            int row = wn * 64 + ntp * 16 + ((lane >> 4) & 1) * 8 + (lane & 7);
            boff[ntp] = (uint32_t)(row * RSTRIDE + 16 * ((lane >> 3) & 1));
        }

        float acc[2][8][4];
#pragma unroll
        for (int mt = 0; mt < 2; mt++)
#pragma unroll
            for (int nt = 0; nt < 8; nt++)
#pragma unroll
                for (int e = 0; e < 4; e++) acc[mt][nt][e] = 0.f;

        for (int c = 0; c < NC; c++) {
            const int s = c % STAGES;
            const uint32_t aA = sb + SM_RING + s * STAGE_BYTES;
            const uint32_t aB = aA + STAGE_A;
            mbar_wait(sb + s * 16, (c / STAGES) & 1);              // wait full

#pragma unroll
            for (int ks = 0; ks < 4; ks++) {
                uint32_t a[2][2][4], b[2][8][2];
#pragma unroll
                for (int pl = 0; pl < 2; pl++)
#pragma unroll
                    for (int mt = 0; mt < 2; mt++)
                        LDSM4(a[pl][mt], aA + pl * A_PL + ks * 32 + aoff[mt]);
#pragma unroll
                for (int pl = 0; pl < 2; pl++)
#pragma unroll
                    for (int ntp = 0; ntp < 4; ntp++) {
                        uint32_t t4[4];
                        LDSM4(t4, aB + pl * B_PL + ks * 32 + boff[ntp]);
                        b[pl][2 * ntp][0]     = t4[0];
                        b[pl][2 * ntp][1]     = t4[1];
                        b[pl][2 * ntp + 1][0] = t4[2];
                        b[pl][2 * ntp + 1][1] = t4[3];
                    }
                const int CA[3] = {0, 0, 1};
                const int CB[3] = {0, 1, 0};
#pragma unroll
                for (int q = 0; q < 3; q++)
#pragma unroll
                    for (int mt = 0; mt < 2; mt++)
#pragma unroll
                        for (int nt = 0; nt < 8; nt++)
                            MMA16816(acc[mt][nt], a[CA[q]][mt], b[CB[q]][nt]);
            }
            mbar_arrive(sb + s * 16 + 8);                          // arrive empty
        }

        __syncthreads();   // ring dead, safe to reuse
        float* acc_s = (float*)(smem + SM_RING);
#pragma unroll
        for (int mt = 0; mt < 2; mt++)
#pragma unroll
            for (int nt = 0; nt < 8; nt++) {
                int r   = wm * 32 + mt * 16 + (lane >> 2);
                int col = wn * 64 + nt * 8 + (lane & 3) * 2;
                acc_s[r * AS + col]           = acc[mt][nt][0];
                acc_s[r * AS + col + 1]       = acc[mt][nt][1];
                acc_s[(r + 8) * AS + col]     = acc[mt][nt][2];
                acc_s[(r + 8) * AS + col + 1] = acc[mt][nt][3];
            }
    }
    if (wid >= 4) __syncthreads();   // producers join the same barrier

    // ---- noise_u tile (all threads) ----
    float* acc_s = (float*)(smem + SM_RING);
    float* su    = acc_s + TM * AS;
    {
        const float* ug = u + (size_t)m0 * NEXP;
        for (int q = tid; q < TM * NEXP; q += NTHREADS) {
            int r = q >> 6, cn = q & 63;
            su[r * US + cn] = ug[(size_t)r * NEXP + cn];
        }
    }
    __syncthreads();

    // ---- per-token epilogue ----
    if (tid < TM) {
        const int m = m0 + tid;
        float* row = acc_s + tid * AS;
        const float* urow = su + tid * US;

        float v1 = -INFINITY, v2 = -INFINITY;
        int i1 = 0, i2 = 0;
        for (int e = 0; e < NEXP; e++) {
            float lg = row[e] * INVSCALE + rb[e];
            float nz = row[NEXP + e] * INVSCALE + nb[e];
            float sp = fmaxf(nz, 0.f) + log1pf(expf(-fabsf(nz)));
            float nv = lg + sp * urow[e];
            if (nv > v1) { v2 = v1; i2 = i1; v1 = nv; i1 = e; }
            else if (nv > v2) { v2 = nv; i2 = e; }
        }
        float e2 = expf(v2 - v1);
        float den = 1.f + e2;
        float p1 = 1.f / den;
        float p2 = e2 / den;

        for (int e = 0; e < NEXP; e++) row[e] = 0.f;
        row[i1] = p1;
        row[i2] = p2;

        float* oid = out + (size_t)M * NEXP;
        oid[(size_t)m * 2 + 0] = (float)i1;
        oid[(size_t)m * 2 + 1] = (float)i2;
    }
    __syncthreads();

    // coalesced probability writeback
    for (int t = tid; t < TM * (NEXP / 4); t += NTHREADS) {
        int r = t >> 4;
        int c4 = (t & 15) * 4;
        float4 v = make_float4(acc_s[r * AS + c4 + 0],
                               acc_s[r * AS + c4 + 1],
                               acc_s[r * AS + c4 + 2],
                               acc_s[r * AS + c4 + 3]);
        *(float4*)(out + (size_t)(m0 + r) * NEXP + c4) = v;
    }
}

extern "C" void kernel_launch(void* const* d_in, const int* in_sizes, int n_in,
                              void* d_out, int out_size)
{
    const float* x  = (const float*)d_in[0];
    const float* rw = (const float*)d_in[1];
    const float* rb = (const float*)d_in[2];
    const float* nw = (const float*)d_in[3];
    const float* nb = (const float*)d_in[4];
    const float* u  = (const float*)d_in[5];

    const int M = in_sizes[0] / DDIM;  // 16384

    static bool attr_set = false;
    if (!attr_set) {
        cudaFuncSetAttribute(router_hmma_kernel,
                             cudaFuncAttributeMaxDynamicSharedMemorySize,
                             SMEM_BYTES);
        attr_set = true;
    }

    prep_w_kernel<<<(NCOL * DDIM) / 256, 256>>>(rw, nw);
    router_hmma_kernel<<<M / TM, NTHREADS, SMEM_BYTES>>>(x, rb, nb, u, (float*)d_out, M);
}